// round 15
// baseline (speedup 1.0000x reference)
#include <cuda_runtime.h>
#include <cstdint>

// ---------------------------------------------------------------------------
// DilatedReparamBlock fused: merge 7 BN(dwconv) branches into one exact 13x13
// depthwise conv + bias, then one packed-fp32 (fma.rn.f32x2) conv.
// R15: even/odd-lane FFMA2 + weight-outer sliding window with ND=3 passes
// ({0,1,2},{3,4,5},{6}), explicit buffer refs + unrolled 3-step rotation
// (no pointer arrays -> no local-mem demotion). Row visits 58 -> 43.
// x: [16, 384, 56, 56] fp32 -> out same shape.
// ---------------------------------------------------------------------------

#define C_CH 384
#define NB 16
#define HW 56
#define PAD 6
#define PH 68                  // padded row stride (272B; rows 16B-aligned)
#define IMG_PER_BLK 4
#define THREADS 224            // 4 images * 56 threads (7 x-tiles * 8 y-tiles)
#define WSTRIDE 16             // u64/weight row: [wpE 0..6, pad, wpO 0..6, pad]
#define W_U64_PER_IMG (13 * WSTRIDE)                   // 208
#define SMEM_IN_BYTES (IMG_PER_BLK * PH * PH * 4)      // 73984
#define SMEM_W_BYTES  (IMG_PER_BLK * W_U64_PER_IMG * 8)// 6656
#define SMEM_BYTES    (SMEM_IN_BYTES + SMEM_W_BYTES)   // 80640

typedef unsigned long long u64;

// Merged weight PAIRS per channel/row: wpE[k]=(w2k,w2k+1) k=0..5, wpE[6]=(w12,0)
// at u64 slots 0..6; wpO[0]=(0,w0), wpO[k]=(w2k-1,w2k) k=1..6 at slots 8..14.
__device__ u64 g_Wd[C_CH * W_U64_PER_IMG];
__device__ float g_bias[C_CH];

// ---------------------------------------------------------------------------
// Kernel 1: fold the 7 BN(dwconv) branches into one 13x13 kernel + bias,
// then emit the even/odd weight-pair layout.
// ---------------------------------------------------------------------------
__global__ void merge_kernel(const float* __restrict__ w_lk,
                             const float* __restrict__ w_b0,
                             const float* __restrict__ w_b1,
                             const float* __restrict__ w_b2,
                             const float* __restrict__ w_b3,
                             const float* __restrict__ w_b4,
                             const float* __restrict__ w_b5,
                             const float* __restrict__ gamma,
                             const float* __restrict__ beta,
                             const float* __restrict__ mean,
                             const float* __restrict__ var) {
    __shared__ float v[169];
    int c = blockIdx.x;
    int t = threadIdx.x;

    float inv[7];
#pragma unroll
    for (int m = 0; m < 7; m++)
        inv[m] = gamma[m * C_CH + c] * rsqrtf(var[m * C_CH + c] + 1e-5f);

    if (t < 169) {
        int i = t / 13, j = t % 13;
        float val = inv[0] * w_lk[c * 169 + t];

        const float* ws[6] = {w_b0, w_b1, w_b2, w_b3, w_b4, w_b5};
        const int ks[6] = {5, 7, 7, 3, 3, 3};
        const int rs[6] = {1, 1, 2, 3, 4, 5};
#pragma unroll
        for (int b = 0; b < 6; b++) {
            int k = ks[b], r = rs[b];
            int span = r * (k - 1) + 1;
            int off = (13 - span) / 2;           // center the dilated kernel
            int ai = i - off, aj = j - off;
            if (ai >= 0 && aj >= 0 && (ai % r) == 0 && (aj % r) == 0) {
                int a = ai / r, bb = aj / r;
                if (a < k && bb < k)
                    val += inv[b + 1] * ws[b][c * k * k + a * k + bb];
            }
        }
        v[t] = val;
    }
    __syncthreads();

    if (t < 91) {                       // wpE: i = t/7, k = t%7
        int i = t / 7, k = t % 7;
        float lo = v[i * 13 + 2 * k];   // 2k <= 12
        float hi = (2 * k + 1 < 13) ? v[i * 13 + 2 * k + 1] : 0.f;
        float2 d2 = make_float2(lo, hi);
        g_Wd[c * W_U64_PER_IMG + i * WSTRIDE + k] = *reinterpret_cast<u64*>(&d2);
    } else if (t < 182) {               // wpO: slots 8..14
        int u = t - 91;
        int i = u / 7, k = u % 7;
        float lo = (k == 0) ? 0.f : v[i * 13 + 2 * k - 1];
        float hi = (k == 0) ? v[i * 13] : v[i * 13 + 2 * k];
        float2 d2 = make_float2(lo, hi);
        g_Wd[c * W_U64_PER_IMG + i * WSTRIDE + 8 + k] = *reinterpret_cast<u64*>(&d2);
    } else if (t < 208) {               // zero pad slots 7 and 15
        int u = t - 182;                // 0..25
        int i = u / 2;
        int slot = 7 + (u % 2) * 8;
        g_Wd[c * W_U64_PER_IMG + i * WSTRIDE + slot] = 0ull;
    }
    if (t == 0) {
        float bsum = 0.f;
#pragma unroll
        for (int m = 0; m < 7; m++)
            bsum += beta[m * C_CH + c] - mean[m * C_CH + c] * inv[m];
        g_bias[c] = bsum;
    }
}

// ---------------------------------------------------------------------------
// FFMA2 (PTX-only on sm_103a). Operands are compiler-visible u64 pairs.
// ---------------------------------------------------------------------------
__device__ __forceinline__ u64 pack2(float lo, float hi) {
    float2 tv = make_float2(lo, hi);
    return *reinterpret_cast<u64*>(&tv);
}
__device__ __forceinline__ void fma2(u64& a, u64 x, u64 w) {
    asm("fma.rn.f32x2 %0, %1, %2, %0;" : "+l"(a) : "l"(x), "l"(w));
}

// Load one padded input row (20 floats) as 5x LDS.128; the 10 aligned
// float2 pair-operands are the float4 halves -- no packing instructions.
__device__ __forceinline__ void load5(float4 (&f)[5], const float* rowptr) {
    const float4* rp = reinterpret_cast<const float4*>(rowptr);
#pragma unroll
    for (int k = 0; k < 5; k++) f[k] = rp[k];
}

// ---------------------------------------------------------------------------
// One weight-row step applied to THREE input-row buffers (explicit refs).
// acc0/1/2 accumulate (even,odd) partials of output rows dfirst+0/1/2;
// at weight row w they consume input rows w, w+1, w+2 respectively.
// Weight row loaded ONCE: wE phase then wO phase (7 u64 live per phase).
// ---------------------------------------------------------------------------
__device__ __forceinline__ void step3(u64 (&acc0)[8], u64 (&acc1)[8],
                                      u64 (&acc2)[8],
                                      const float4 (&F0)[5],
                                      const float4 (&F1)[5],
                                      const float4 (&F2)[5],
                                      const u64* __restrict__ wr) {
    const u64* f0 = reinterpret_cast<const u64*>(F0);
    const u64* f1 = reinterpret_cast<const u64*>(F1);
    const u64* f2 = reinterpret_cast<const u64*>(F2);

    {   // even-tap phase
        const ulonglong2* e2 = reinterpret_cast<const ulonglong2*>(wr);
        ulonglong2 t0 = e2[0], t1 = e2[1], t2 = e2[2];   // 3x LDS.128
        u64 wE[7] = {t0.x, t0.y, t1.x, t1.y, t2.x, t2.y, wr[6]};
#pragma unroll
        for (int e = 0; e < 4; e++)
#pragma unroll
            for (int k = 0; k < 7; k++) {
                fma2(acc0[2 * e], f0[e + k], wE[k]);
                fma2(acc1[2 * e], f1[e + k], wE[k]);
                fma2(acc2[2 * e], f2[e + k], wE[k]);
            }
    }
    {   // odd-tap phase
        const ulonglong2* o2 = reinterpret_cast<const ulonglong2*>(wr + 8);
        ulonglong2 t0 = o2[0], t1 = o2[1], t2 = o2[2];   // 3x LDS.128
        u64 wO[7] = {t0.x, t0.y, t1.x, t1.y, t2.x, t2.y, wr[14]};
#pragma unroll
        for (int o = 0; o < 4; o++)
#pragma unroll
            for (int k = 0; k < 7; k++) {
                fma2(acc0[2 * o + 1], f0[o + k], wO[k]);
                fma2(acc1[2 * o + 1], f1[o + k], wO[k]);
                fma2(acc2[2 * o + 1], f2[o + k], wO[k]);
            }
    }
}

// One weight-row step applied to ONE input-row buffer.
__device__ __forceinline__ void step1(u64 (&acc)[8],
                                      const float4 (&F)[5],
                                      const u64* __restrict__ wr) {
    const u64* f = reinterpret_cast<const u64*>(F);
    {
        const ulonglong2* e2 = reinterpret_cast<const ulonglong2*>(wr);
        ulonglong2 t0 = e2[0], t1 = e2[1], t2 = e2[2];
        u64 wE[7] = {t0.x, t0.y, t1.x, t1.y, t2.x, t2.y, wr[6]};
#pragma unroll
        for (int e = 0; e < 4; e++)
#pragma unroll
            for (int k = 0; k < 7; k++)
                fma2(acc[2 * e], f[e + k], wE[k]);
    }
    {
        const ulonglong2* o2 = reinterpret_cast<const ulonglong2*>(wr + 8);
        ulonglong2 t0 = o2[0], t1 = o2[1], t2 = o2[2];
        u64 wO[7] = {t0.x, t0.y, t1.x, t1.y, t2.x, t2.y, wr[14]};
#pragma unroll
        for (int o = 0; o < 4; o++)
#pragma unroll
            for (int k = 0; k < 7; k++)
                fma2(acc[2 * o + 1], f[o + k], wO[k]);
    }
}

// Horizontal-reduce one output row (lo+hi) and store as 2x STG.128.
__device__ __forceinline__ void store_row(float* obase, int row,
                                          const u64 (&acc)[8]) {
    float o[8];
#pragma unroll
    for (int x = 0; x < 8; x++) {
        float2 v = *reinterpret_cast<const float2*>(&acc[x]);
        o[x] = v.x + v.y;
    }
    float4* orow = reinterpret_cast<float4*>(obase + row * HW);
    orow[0] = make_float4(o[0], o[1], o[2], o[3]);
    orow[1] = make_float4(o[4], o[5], o[6], o[7]);
}

// ---------------------------------------------------------------------------
// Kernel 2: depthwise 13x13 conv + bias.
// Block = 4 (n,c) images. Per image: 56 threads = 7 x-tiles (8 wide) x 8 ty.
// Thread strip = 8 wide x 7 rows; passes d = {0,1,2},{3,4,5},{6}.
// Each pass walks weight rows 0..12; the 3-buffer input ring slides one row
// per step; rotation unrolled 3 steps (roles compile-time, no demotion).
// ---------------------------------------------------------------------------
extern __shared__ char s_raw[];

__global__ __launch_bounds__(THREADS, 2)
void conv13_kernel(const float* __restrict__ x, float* __restrict__ out) {
    float* s_in = reinterpret_cast<float*>(s_raw);
    u64* s_w = reinterpret_cast<u64*>(s_raw + SMEM_IN_BYTES);

    int t = threadIdx.x;
    int img_l = t / 56;
    int s = t % 56;
    int tx = s % 7, ty = s / 7;
    int x0 = tx * 8;
    int y0 = ty * 7;

    int img = blockIdx.x * IMG_PER_BLK + img_l;   // flat (n*C + c)
    int c = img % C_CH;

    float* my = s_in + img_l * (PH * PH);
    u64* mw = s_w + img_l * W_U64_PER_IMG;
    const float* gx = x + (size_t)img * (HW * HW);

    // Stage merged weight pairs: 208 u64 = 104 ulonglong2 per image (guarded).
    {
        const ulonglong2* src =
            reinterpret_cast<const ulonglong2*>(g_Wd + (size_t)c * W_U64_PER_IMG);
        ulonglong2* dst = reinterpret_cast<ulonglong2*>(mw);
        for (int k = s; k < W_U64_PER_IMG / 2; k += 56)
            dst[k] = __ldg(src + k);
    }

    // Stage input: vector zero-fill padded tile, then coalesced float2
    // interior copy (constant-divisor indexing, no runtime div).
    {
        float4* z = reinterpret_cast<float4*>(my);
        for (int k = s; k < (PH * PH) / 4; k += 56)        // 1156 float4
            z[k] = make_float4(0.f, 0.f, 0.f, 0.f);
    }
    __syncthreads();
    {
        int col2 = s % 28;          // column pair 0..27
        int r0 = s / 28;            // 0 or 1
        const float2* g2 = reinterpret_cast<const float2*>(gx);
#pragma unroll
        for (int k = 0; k < 28; k++) {
            int r = r0 + 2 * k;
            float2 v = __ldg(g2 + r * 28 + col2);
            *reinterpret_cast<float2*>(my + (r + PAD) * PH + PAD + 2 * col2) = v;
        }
    }
    __syncthreads();

    float bb = __ldg(&g_bias[c]);
    u64 biasE = pack2(bb, 0.f);     // bias in even lane; lo+hi adds it once

    const float* rbase = my + y0 * PH + x0;   // padded coords, 16B aligned
    float* obase = out + (size_t)img * (HW * HW) + x0;

    // ============ Passes 1 & 2: ND=3, dfirst = 0 then 3 ====================
#pragma unroll 1
    for (int dfirst = 0; dfirst < 6; dfirst += 3) {
        u64 acc0[8], acc1[8], acc2[8];
#pragma unroll
        for (int q = 0; q < 8; q++) {
            acc0[q] = biasE; acc1[q] = biasE; acc2[q] = biasE;
        }

        const float* rb = rbase + dfirst * PH;
        float4 A[5], B[5], C[5];
        load5(A, rb + 0 * PH);
        load5(B, rb + 1 * PH);
        load5(C, rb + 2 * PH);

#pragma unroll 1
        for (int w = 0; w < 12; w += 3) {
            // step w:   rows w, w+1, w+2  = A, B, C
            step3(acc0, acc1, acc2, A, B, C, mw + w * WSTRIDE);
            load5(A, rb + (w + 3) * PH);
            // step w+1: rows w+1..w+3     = B, C, A
            step3(acc0, acc1, acc2, B, C, A, mw + (w + 1) * WSTRIDE);
            load5(B, rb + (w + 4) * PH);
            // step w+2: rows w+2..w+4     = C, A, B
            step3(acc0, acc1, acc2, C, A, B, mw + (w + 2) * WSTRIDE);
            load5(C, rb + (w + 5) * PH);
        }
        // tail w=12: rows 12,13,14 = A, B, C
        step3(acc0, acc1, acc2, A, B, C, mw + 12 * WSTRIDE);

        store_row(obase, y0 + dfirst + 0, acc0);
        store_row(obase, y0 + dfirst + 1, acc1);
        store_row(obase, y0 + dfirst + 2, acc2);
    }

    // ============ Pass 3: ND=1, d = 6 (rows 6..18) =========================
    {
        u64 acc[8];
#pragma unroll
        for (int q = 0; q < 8; q++) acc[q] = biasE;

        const float* rb = rbase + 6 * PH;
        float4 A[5], B[5];
        load5(A, rb + 0 * PH);

#pragma unroll 1
        for (int w = 0; w < 12; w += 2) {
            load5(B, rb + (w + 1) * PH);
            step1(acc, A, mw + w * WSTRIDE);           // row 6+w
            load5(A, rb + (w + 2) * PH);
            step1(acc, B, mw + (w + 1) * WSTRIDE);     // row 7+w
        }
        step1(acc, A, mw + 12 * WSTRIDE);              // row 18

        store_row(obase, y0 + 6, acc);
    }
}

// ---------------------------------------------------------------------------
extern "C" void kernel_launch(void* const* d_in, const int* in_sizes, int n_in,
                              void* d_out, int out_size) {
    const float* x    = (const float*)d_in[0];
    const float* w_lk = (const float*)d_in[1];
    const float* w_b0 = (const float*)d_in[2];
    const float* w_b1 = (const float*)d_in[3];
    const float* w_b2 = (const float*)d_in[4];
    const float* w_b3 = (const float*)d_in[5];
    const float* w_b4 = (const float*)d_in[6];
    const float* w_b5 = (const float*)d_in[7];
    const float* gam  = (const float*)d_in[8];
    const float* bet  = (const float*)d_in[9];
    const float* mea  = (const float*)d_in[10];
    const float* var  = (const float*)d_in[11];
    float* out = (float*)d_out;

    merge_kernel<<<C_CH, 224>>>(w_lk, w_b0, w_b1, w_b2, w_b3, w_b4, w_b5,
                                gam, bet, mea, var);

    cudaFuncSetAttribute(conv13_kernel,
                         cudaFuncAttributeMaxDynamicSharedMemorySize,
                         SMEM_BYTES);
    int grid = (NB * C_CH) / IMG_PER_BLK;  // 1536
    conv13_kernel<<<grid, THREADS, SMEM_BYTES>>>(x, out);
}

// round 16
// speedup vs baseline: 1.1797x; 1.1797x over previous
#include <cuda_runtime.h>
#include <cstdint>

// ---------------------------------------------------------------------------
// DilatedReparamBlock fused: merge 7 BN(dwconv) branches into one exact 13x13
// depthwise conv + bias, then one packed-fp32 (fma.rn.f32x2) conv.
// R16 = R15 kernel body (even/odd-lane FFMA2, weight-outer ND=3 sliding ring,
// explicit buffer rotation) with a register-friendly launch shape:
// 2 images x 112 threads, __launch_bounds__(112, 3) -> 195-reg cap so the
// ND=3 ring does NOT spill. x: [16, 384, 56, 56] fp32 -> out same shape.
// ---------------------------------------------------------------------------

#define C_CH 384
#define NB 16
#define HW 56
#define PAD 6
#define PH 68                  // padded row stride (272B; rows 16B-aligned)
#define IMG_PER_BLK 2
#define THREADS 112            // 2 images * 56 threads (7 x-tiles * 8 y-tiles)
#define WSTRIDE 16             // u64/weight row: [wpE 0..6, pad, wpO 0..6, pad]
#define W_U64_PER_IMG (13 * WSTRIDE)                   // 208
#define SMEM_IN_BYTES (IMG_PER_BLK * PH * PH * 4)      // 36992
#define SMEM_W_BYTES  (IMG_PER_BLK * W_U64_PER_IMG * 8)// 3328
#define SMEM_BYTES    (SMEM_IN_BYTES + SMEM_W_BYTES)   // 40320

typedef unsigned long long u64;

// Merged weight PAIRS per channel/row: wpE[k]=(w2k,w2k+1) k=0..5, wpE[6]=(w12,0)
// at u64 slots 0..6; wpO[0]=(0,w0), wpO[k]=(w2k-1,w2k) k=1..6 at slots 8..14.
__device__ u64 g_Wd[C_CH * W_U64_PER_IMG];
__device__ float g_bias[C_CH];

// ---------------------------------------------------------------------------
// Kernel 1: fold the 7 BN(dwconv) branches into one 13x13 kernel + bias,
// then emit the even/odd weight-pair layout.
// ---------------------------------------------------------------------------
__global__ void merge_kernel(const float* __restrict__ w_lk,
                             const float* __restrict__ w_b0,
                             const float* __restrict__ w_b1,
                             const float* __restrict__ w_b2,
                             const float* __restrict__ w_b3,
                             const float* __restrict__ w_b4,
                             const float* __restrict__ w_b5,
                             const float* __restrict__ gamma,
                             const float* __restrict__ beta,
                             const float* __restrict__ mean,
                             const float* __restrict__ var) {
    __shared__ float v[169];
    int c = blockIdx.x;
    int t = threadIdx.x;

    float inv[7];
#pragma unroll
    for (int m = 0; m < 7; m++)
        inv[m] = gamma[m * C_CH + c] * rsqrtf(var[m * C_CH + c] + 1e-5f);

    if (t < 169) {
        int i = t / 13, j = t % 13;
        float val = inv[0] * w_lk[c * 169 + t];

        const float* ws[6] = {w_b0, w_b1, w_b2, w_b3, w_b4, w_b5};
        const int ks[6] = {5, 7, 7, 3, 3, 3};
        const int rs[6] = {1, 1, 2, 3, 4, 5};
#pragma unroll
        for (int b = 0; b < 6; b++) {
            int k = ks[b], r = rs[b];
            int span = r * (k - 1) + 1;
            int off = (13 - span) / 2;           // center the dilated kernel
            int ai = i - off, aj = j - off;
            if (ai >= 0 && aj >= 0 && (ai % r) == 0 && (aj % r) == 0) {
                int a = ai / r, bb = aj / r;
                if (a < k && bb < k)
                    val += inv[b + 1] * ws[b][c * k * k + a * k + bb];
            }
        }
        v[t] = val;
    }
    __syncthreads();

    if (t < 91) {                       // wpE: i = t/7, k = t%7
        int i = t / 7, k = t % 7;
        float lo = v[i * 13 + 2 * k];   // 2k <= 12
        float hi = (2 * k + 1 < 13) ? v[i * 13 + 2 * k + 1] : 0.f;
        float2 d2 = make_float2(lo, hi);
        g_Wd[c * W_U64_PER_IMG + i * WSTRIDE + k] = *reinterpret_cast<u64*>(&d2);
    } else if (t < 182) {               // wpO: slots 8..14
        int u = t - 91;
        int i = u / 7, k = u % 7;
        float lo = (k == 0) ? 0.f : v[i * 13 + 2 * k - 1];
        float hi = (k == 0) ? v[i * 13] : v[i * 13 + 2 * k];
        float2 d2 = make_float2(lo, hi);
        g_Wd[c * W_U64_PER_IMG + i * WSTRIDE + 8 + k] = *reinterpret_cast<u64*>(&d2);
    } else if (t < 208) {               // zero pad slots 7 and 15
        int u = t - 182;                // 0..25
        int i = u / 2;
        int slot = 7 + (u % 2) * 8;
        g_Wd[c * W_U64_PER_IMG + i * WSTRIDE + slot] = 0ull;
    }
    if (t == 0) {
        float bsum = 0.f;
#pragma unroll
        for (int m = 0; m < 7; m++)
            bsum += beta[m * C_CH + c] - mean[m * C_CH + c] * inv[m];
        g_bias[c] = bsum;
    }
}

// ---------------------------------------------------------------------------
// FFMA2 (PTX-only on sm_103a). Operands are compiler-visible u64 pairs.
// ---------------------------------------------------------------------------
__device__ __forceinline__ u64 pack2(float lo, float hi) {
    float2 tv = make_float2(lo, hi);
    return *reinterpret_cast<u64*>(&tv);
}
__device__ __forceinline__ void fma2(u64& a, u64 x, u64 w) {
    asm("fma.rn.f32x2 %0, %1, %2, %0;" : "+l"(a) : "l"(x), "l"(w));
}

// Load one padded input row (20 floats) as 5x LDS.128; the 10 aligned
// float2 pair-operands are the float4 halves -- no packing instructions.
__device__ __forceinline__ void load5(float4 (&f)[5], const float* rowptr) {
    const float4* rp = reinterpret_cast<const float4*>(rowptr);
#pragma unroll
    for (int k = 0; k < 5; k++) f[k] = rp[k];
}

// ---------------------------------------------------------------------------
// One weight-row step applied to THREE input-row buffers (explicit refs).
// acc0/1/2 accumulate (even,odd) partials of output rows dfirst+0/1/2;
// at weight row w they consume input rows w, w+1, w+2 respectively.
// Weight row loaded ONCE: wE phase then wO phase (7 u64 live per phase).
// ---------------------------------------------------------------------------
__device__ __forceinline__ void step3(u64 (&acc0)[8], u64 (&acc1)[8],
                                      u64 (&acc2)[8],
                                      const float4 (&F0)[5],
                                      const float4 (&F1)[5],
                                      const float4 (&F2)[5],
                                      const u64* __restrict__ wr) {
    const u64* f0 = reinterpret_cast<const u64*>(F0);
    const u64* f1 = reinterpret_cast<const u64*>(F1);
    const u64* f2 = reinterpret_cast<const u64*>(F2);

    {   // even-tap phase
        const ulonglong2* e2 = reinterpret_cast<const ulonglong2*>(wr);
        ulonglong2 t0 = e2[0], t1 = e2[1], t2 = e2[2];   // 3x LDS.128
        u64 wE[7] = {t0.x, t0.y, t1.x, t1.y, t2.x, t2.y, wr[6]};
#pragma unroll
        for (int e = 0; e < 4; e++)
#pragma unroll
            for (int k = 0; k < 7; k++) {
                fma2(acc0[2 * e], f0[e + k], wE[k]);
                fma2(acc1[2 * e], f1[e + k], wE[k]);
                fma2(acc2[2 * e], f2[e + k], wE[k]);
            }
    }
    {   // odd-tap phase
        const ulonglong2* o2 = reinterpret_cast<const ulonglong2*>(wr + 8);
        ulonglong2 t0 = o2[0], t1 = o2[1], t2 = o2[2];   // 3x LDS.128
        u64 wO[7] = {t0.x, t0.y, t1.x, t1.y, t2.x, t2.y, wr[14]};
#pragma unroll
        for (int o = 0; o < 4; o++)
#pragma unroll
            for (int k = 0; k < 7; k++) {
                fma2(acc0[2 * o + 1], f0[o + k], wO[k]);
                fma2(acc1[2 * o + 1], f1[o + k], wO[k]);
                fma2(acc2[2 * o + 1], f2[o + k], wO[k]);
            }
    }
}

// One weight-row step applied to ONE input-row buffer.
__device__ __forceinline__ void step1(u64 (&acc)[8],
                                      const float4 (&F)[5],
                                      const u64* __restrict__ wr) {
    const u64* f = reinterpret_cast<const u64*>(F);
    {
        const ulonglong2* e2 = reinterpret_cast<const ulonglong2*>(wr);
        ulonglong2 t0 = e2[0], t1 = e2[1], t2 = e2[2];
        u64 wE[7] = {t0.x, t0.y, t1.x, t1.y, t2.x, t2.y, wr[6]};
#pragma unroll
        for (int e = 0; e < 4; e++)
#pragma unroll
            for (int k = 0; k < 7; k++)
                fma2(acc[2 * e], f[e + k], wE[k]);
    }
    {
        const ulonglong2* o2 = reinterpret_cast<const ulonglong2*>(wr + 8);
        ulonglong2 t0 = o2[0], t1 = o2[1], t2 = o2[2];
        u64 wO[7] = {t0.x, t0.y, t1.x, t1.y, t2.x, t2.y, wr[14]};
#pragma unroll
        for (int o = 0; o < 4; o++)
#pragma unroll
            for (int k = 0; k < 7; k++)
                fma2(acc[2 * o + 1], f[o + k], wO[k]);
    }
}

// Horizontal-reduce one output row (lo+hi) and store as 2x STG.128.
__device__ __forceinline__ void store_row(float* obase, int row,
                                          const u64 (&acc)[8]) {
    float o[8];
#pragma unroll
    for (int x = 0; x < 8; x++) {
        float2 v = *reinterpret_cast<const float2*>(&acc[x]);
        o[x] = v.x + v.y;
    }
    float4* orow = reinterpret_cast<float4*>(obase + row * HW);
    orow[0] = make_float4(o[0], o[1], o[2], o[3]);
    orow[1] = make_float4(o[4], o[5], o[6], o[7]);
}

// ---------------------------------------------------------------------------
// Kernel 2: depthwise 13x13 conv + bias.
// Block = 2 (n,c) images. Per image: 56 threads = 7 x-tiles (8 wide) x 8 ty.
// Thread strip = 8 wide x 7 rows; passes d = {0,1,2},{3,4,5},{6}.
// Each pass walks weight rows 0..12; the 3-buffer input ring slides one row
// per step; rotation unrolled 3 steps (roles compile-time, no demotion).
// __launch_bounds__(112, 3) -> 336 thr/SM -> 195-reg cap: ND=3 fits, no spill.
// ---------------------------------------------------------------------------
extern __shared__ char s_raw[];

__global__ __launch_bounds__(THREADS, 3)
void conv13_kernel(const float* __restrict__ x, float* __restrict__ out) {
    float* s_in = reinterpret_cast<float*>(s_raw);
    u64* s_w = reinterpret_cast<u64*>(s_raw + SMEM_IN_BYTES);

    int t = threadIdx.x;
    int img_l = t / 56;
    int s = t % 56;
    int tx = s % 7, ty = s / 7;
    int x0 = tx * 8;
    int y0 = ty * 7;

    int img = blockIdx.x * IMG_PER_BLK + img_l;   // flat (n*C + c)
    int c = img % C_CH;

    float* my = s_in + img_l * (PH * PH);
    u64* mw = s_w + img_l * W_U64_PER_IMG;
    const float* gx = x + (size_t)img * (HW * HW);

    // Stage merged weight pairs: 208 u64 = 104 ulonglong2 per image (guarded).
    {
        const ulonglong2* src =
            reinterpret_cast<const ulonglong2*>(g_Wd + (size_t)c * W_U64_PER_IMG);
        ulonglong2* dst = reinterpret_cast<ulonglong2*>(mw);
        for (int k = s; k < W_U64_PER_IMG / 2; k += 56)
            dst[k] = __ldg(src + k);
    }

    // Stage input: vector zero-fill padded tile, then coalesced float2
    // interior copy (constant-divisor indexing, no runtime div).
    {
        float4* z = reinterpret_cast<float4*>(my);
        for (int k = s; k < (PH * PH) / 4; k += 56)        // 1156 float4
            z[k] = make_float4(0.f, 0.f, 0.f, 0.f);
    }
    __syncthreads();
    {
        int col2 = s % 28;          // column pair 0..27
        int r0 = s / 28;            // 0 or 1
        const float2* g2 = reinterpret_cast<const float2*>(gx);
#pragma unroll
        for (int k = 0; k < 28; k++) {
            int r = r0 + 2 * k;
            float2 v = __ldg(g2 + r * 28 + col2);
            *reinterpret_cast<float2*>(my + (r + PAD) * PH + PAD + 2 * col2) = v;
        }
    }
    __syncthreads();

    float bb = __ldg(&g_bias[c]);
    u64 biasE = pack2(bb, 0.f);     // bias in even lane; lo+hi adds it once

    const float* rbase = my + y0 * PH + x0;   // padded coords, 16B aligned
    float* obase = out + (size_t)img * (HW * HW) + x0;

    // ============ Passes 1 & 2: ND=3, dfirst = 0 then 3 ====================
#pragma unroll 1
    for (int dfirst = 0; dfirst < 6; dfirst += 3) {
        u64 acc0[8], acc1[8], acc2[8];
#pragma unroll
        for (int q = 0; q < 8; q++) {
            acc0[q] = biasE; acc1[q] = biasE; acc2[q] = biasE;
        }

        const float* rb = rbase + dfirst * PH;
        float4 A[5], B[5], C[5];
        load5(A, rb + 0 * PH);
        load5(B, rb + 1 * PH);
        load5(C, rb + 2 * PH);

#pragma unroll 1
        for (int w = 0; w < 12; w += 3) {
            // step w:   rows w, w+1, w+2  = A, B, C
            step3(acc0, acc1, acc2, A, B, C, mw + w * WSTRIDE);
            load5(A, rb + (w + 3) * PH);
            // step w+1: rows w+1..w+3     = B, C, A
            step3(acc0, acc1, acc2, B, C, A, mw + (w + 1) * WSTRIDE);
            load5(B, rb + (w + 4) * PH);
            // step w+2: rows w+2..w+4     = C, A, B
            step3(acc0, acc1, acc2, C, A, B, mw + (w + 2) * WSTRIDE);
            load5(C, rb + (w + 5) * PH);
        }
        // tail w=12: rows 12,13,14 = A, B, C
        step3(acc0, acc1, acc2, A, B, C, mw + 12 * WSTRIDE);

        store_row(obase, y0 + dfirst + 0, acc0);
        store_row(obase, y0 + dfirst + 1, acc1);
        store_row(obase, y0 + dfirst + 2, acc2);
    }

    // ============ Pass 3: ND=1, d = 6 (rows 6..18) =========================
    {
        u64 acc[8];
#pragma unroll
        for (int q = 0; q < 8; q++) acc[q] = biasE;

        const float* rb = rbase + 6 * PH;
        float4 A[5], B[5];
        load5(A, rb + 0 * PH);

#pragma unroll 1
        for (int w = 0; w < 12; w += 2) {
            load5(B, rb + (w + 1) * PH);
            step1(acc, A, mw + w * WSTRIDE);           // row 6+w
            load5(A, rb + (w + 2) * PH);
            step1(acc, B, mw + (w + 1) * WSTRIDE);     // row 7+w
        }
        step1(acc, A, mw + 12 * WSTRIDE);              // row 18

        store_row(obase, y0 + 6, acc);
    }
}

// ---------------------------------------------------------------------------
extern "C" void kernel_launch(void* const* d_in, const int* in_sizes, int n_in,
                              void* d_out, int out_size) {
    const float* x    = (const float*)d_in[0];
    const float* w_lk = (const float*)d_in[1];
    const float* w_b0 = (const float*)d_in[2];
    const float* w_b1 = (const float*)d_in[3];
    const float* w_b2 = (const float*)d_in[4];
    const float* w_b3 = (const float*)d_in[5];
    const float* w_b4 = (const float*)d_in[6];
    const float* w_b5 = (const float*)d_in[7];
    const float* gam  = (const float*)d_in[8];
    const float* bet  = (const float*)d_in[9];
    const float* mea  = (const float*)d_in[10];
    const float* var  = (const float*)d_in[11];
    float* out = (float*)d_out;

    merge_kernel<<<C_CH, 224>>>(w_lk, w_b0, w_b1, w_b2, w_b3, w_b4, w_b5,
                                gam, bet, mea, var);

    cudaFuncSetAttribute(conv13_kernel,
                         cudaFuncAttributeMaxDynamicSharedMemorySize,
                         SMEM_BYTES);
    int grid = (NB * C_CH) / IMG_PER_BLK;  // 3072
    conv13_kernel<<<grid, THREADS, SMEM_BYTES>>>(x, out);
}

// round 17
// speedup vs baseline: 1.2296x; 1.0422x over previous
#include <cuda_runtime.h>
#include <cstdint>

// ---------------------------------------------------------------------------
// DilatedReparamBlock fused: merge 7 BN(dwconv) branches into one exact 13x13
// depthwise conv + bias, then one packed-fp32 (fma.rn.f32x2) conv.
// R17 = R16 (even/odd-lane FFMA2, weight-outer ND=3 ring, 112thr/195-reg cap)
//       + software-pipelined weight loads: wO(w) loads under E-phase(w),
//       wE(w+1) loads under O-phase(w) -> no exposed weight LDS latency.
// x: [16, 384, 56, 56] fp32 -> out same shape.
// ---------------------------------------------------------------------------

#define C_CH 384
#define NB 16
#define HW 56
#define PAD 6
#define PH 68                  // padded row stride (272B; rows 16B-aligned)
#define IMG_PER_BLK 2
#define THREADS 112            // 2 images * 56 threads (7 x-tiles * 8 y-tiles)
#define WSTRIDE 16             // u64/weight row: [wpE 0..6, pad, wpO 0..6, pad]
#define W_U64_PER_IMG (13 * WSTRIDE)                   // 208
#define SMEM_IN_BYTES (IMG_PER_BLK * PH * PH * 4)      // 36992
#define SMEM_W_BYTES  (IMG_PER_BLK * W_U64_PER_IMG * 8)// 3328
#define SMEM_BYTES    (SMEM_IN_BYTES + SMEM_W_BYTES)   // 40320

typedef unsigned long long u64;

// Merged weight PAIRS per channel/row: wpE[k]=(w2k,w2k+1) k=0..5, wpE[6]=(w12,0)
// at u64 slots 0..6; wpO[0]=(0,w0), wpO[k]=(w2k-1,w2k) k=1..6 at slots 8..14.
__device__ u64 g_Wd[C_CH * W_U64_PER_IMG];
__device__ float g_bias[C_CH];

// ---------------------------------------------------------------------------
// Kernel 1: fold the 7 BN(dwconv) branches into one 13x13 kernel + bias,
// then emit the even/odd weight-pair layout.
// ---------------------------------------------------------------------------
__global__ void merge_kernel(const float* __restrict__ w_lk,
                             const float* __restrict__ w_b0,
                             const float* __restrict__ w_b1,
                             const float* __restrict__ w_b2,
                             const float* __restrict__ w_b3,
                             const float* __restrict__ w_b4,
                             const float* __restrict__ w_b5,
                             const float* __restrict__ gamma,
                             const float* __restrict__ beta,
                             const float* __restrict__ mean,
                             const float* __restrict__ var) {
    __shared__ float v[169];
    int c = blockIdx.x;
    int t = threadIdx.x;

    float inv[7];
#pragma unroll
    for (int m = 0; m < 7; m++)
        inv[m] = gamma[m * C_CH + c] * rsqrtf(var[m * C_CH + c] + 1e-5f);

    if (t < 169) {
        int i = t / 13, j = t % 13;
        float val = inv[0] * w_lk[c * 169 + t];

        const float* ws[6] = {w_b0, w_b1, w_b2, w_b3, w_b4, w_b5};
        const int ks[6] = {5, 7, 7, 3, 3, 3};
        const int rs[6] = {1, 1, 2, 3, 4, 5};
#pragma unroll
        for (int b = 0; b < 6; b++) {
            int k = ks[b], r = rs[b];
            int span = r * (k - 1) + 1;
            int off = (13 - span) / 2;           // center the dilated kernel
            int ai = i - off, aj = j - off;
            if (ai >= 0 && aj >= 0 && (ai % r) == 0 && (aj % r) == 0) {
                int a = ai / r, bb = aj / r;
                if (a < k && bb < k)
                    val += inv[b + 1] * ws[b][c * k * k + a * k + bb];
            }
        }
        v[t] = val;
    }
    __syncthreads();

    if (t < 91) {                       // wpE: i = t/7, k = t%7
        int i = t / 7, k = t % 7;
        float lo = v[i * 13 + 2 * k];   // 2k <= 12
        float hi = (2 * k + 1 < 13) ? v[i * 13 + 2 * k + 1] : 0.f;
        float2 d2 = make_float2(lo, hi);
        g_Wd[c * W_U64_PER_IMG + i * WSTRIDE + k] = *reinterpret_cast<u64*>(&d2);
    } else if (t < 182) {               // wpO: slots 8..14
        int u = t - 91;
        int i = u / 7, k = u % 7;
        float lo = (k == 0) ? 0.f : v[i * 13 + 2 * k - 1];
        float hi = (k == 0) ? v[i * 13] : v[i * 13 + 2 * k];
        float2 d2 = make_float2(lo, hi);
        g_Wd[c * W_U64_PER_IMG + i * WSTRIDE + 8 + k] = *reinterpret_cast<u64*>(&d2);
    } else if (t < 208) {               // zero pad slots 7 and 15
        int u = t - 182;                // 0..25
        int i = u / 2;
        int slot = 7 + (u % 2) * 8;
        g_Wd[c * W_U64_PER_IMG + i * WSTRIDE + slot] = 0ull;
    }
    if (t == 0) {
        float bsum = 0.f;
#pragma unroll
        for (int m = 0; m < 7; m++)
            bsum += beta[m * C_CH + c] - mean[m * C_CH + c] * inv[m];
        g_bias[c] = bsum;
    }
}

// ---------------------------------------------------------------------------
// FFMA2 (PTX-only on sm_103a). Operands are compiler-visible u64 pairs.
// ---------------------------------------------------------------------------
__device__ __forceinline__ u64 pack2(float lo, float hi) {
    float2 tv = make_float2(lo, hi);
    return *reinterpret_cast<u64*>(&tv);
}
__device__ __forceinline__ void fma2(u64& a, u64 x, u64 w) {
    asm("fma.rn.f32x2 %0, %1, %2, %0;" : "+l"(a) : "l"(x), "l"(w));
}

// Load one padded input row (20 floats) as 5x LDS.128; the 10 aligned
// float2 pair-operands are the float4 halves -- no packing instructions.
__device__ __forceinline__ void load5(float4 (&f)[5], const float* rowptr) {
    const float4* rp = reinterpret_cast<const float4*>(rowptr);
#pragma unroll
    for (int k = 0; k < 5; k++) f[k] = rp[k];
}

// Load one 7-pair weight half (wE at p, wO at p+8): 3x LDS.128 + 1x LDS.64.
__device__ __forceinline__ void loadW7(u64 (&w7)[7], const u64* __restrict__ p) {
    const ulonglong2* v = reinterpret_cast<const ulonglong2*>(p);
    ulonglong2 a = v[0], b = v[1], cc = v[2];
    w7[0] = a.x;  w7[1] = a.y;  w7[2] = b.x;  w7[3] = b.y;
    w7[4] = cc.x; w7[5] = cc.y; w7[6] = p[6];
}

// ---------------------------------------------------------------------------
// One weight-half phase applied to THREE input-row buffers.
// PAR=0: even outputs acc[2e]; PAR=1: odd outputs acc[2o+1]. Same index math.
// ---------------------------------------------------------------------------
template <int PAR>
__device__ __forceinline__ void phase3(u64 (&a0)[8], u64 (&a1)[8], u64 (&a2)[8],
                                       const float4 (&F0)[5],
                                       const float4 (&F1)[5],
                                       const float4 (&F2)[5],
                                       const u64 (&w7)[7]) {
    const u64* f0 = reinterpret_cast<const u64*>(F0);
    const u64* f1 = reinterpret_cast<const u64*>(F1);
    const u64* f2 = reinterpret_cast<const u64*>(F2);
#pragma unroll
    for (int e = 0; e < 4; e++)
#pragma unroll
        for (int k = 0; k < 7; k++) {
            fma2(a0[2 * e + PAR], f0[e + k], w7[k]);
            fma2(a1[2 * e + PAR], f1[e + k], w7[k]);
            fma2(a2[2 * e + PAR], f2[e + k], w7[k]);
        }
}

template <int PAR>
__device__ __forceinline__ void phase1(u64 (&acc)[8],
                                       const float4 (&F)[5],
                                       const u64 (&w7)[7]) {
    const u64* f = reinterpret_cast<const u64*>(F);
#pragma unroll
    for (int e = 0; e < 4; e++)
#pragma unroll
        for (int k = 0; k < 7; k++)
            fma2(acc[2 * e + PAR], f[e + k], w7[k]);
}

// Horizontal-reduce one output row (lo+hi) and store as 2x STG.128.
__device__ __forceinline__ void store_row(float* obase, int row,
                                          const u64 (&acc)[8]) {
    float o[8];
#pragma unroll
    for (int x = 0; x < 8; x++) {
        float2 v = *reinterpret_cast<const float2*>(&acc[x]);
        o[x] = v.x + v.y;
    }
    float4* orow = reinterpret_cast<float4*>(obase + row * HW);
    orow[0] = make_float4(o[0], o[1], o[2], o[3]);
    orow[1] = make_float4(o[4], o[5], o[6], o[7]);
}

// ---------------------------------------------------------------------------
// Kernel 2: depthwise 13x13 conv + bias.
// Block = 2 (n,c) images. Per image: 56 threads = 7 x-tiles (8 wide) x 8 ty.
// Thread strip = 8 wide x 7 rows; passes d = {0,1,2},{3,4,5},{6}.
// Weight-outer sliding ring; weight halves software-pipelined one phase
// ahead so every LDS has an 84-FFMA2 wall covering its latency.
// ---------------------------------------------------------------------------
extern __shared__ char s_raw[];

__global__ __launch_bounds__(THREADS, 3)
void conv13_kernel(const float* __restrict__ x, float* __restrict__ out) {
    float* s_in = reinterpret_cast<float*>(s_raw);
    u64* s_w = reinterpret_cast<u64*>(s_raw + SMEM_IN_BYTES);

    int t = threadIdx.x;
    int img_l = t / 56;
    int s = t % 56;
    int tx = s % 7, ty = s / 7;
    int x0 = tx * 8;
    int y0 = ty * 7;

    int img = blockIdx.x * IMG_PER_BLK + img_l;   // flat (n*C + c)
    int c = img % C_CH;

    float* my = s_in + img_l * (PH * PH);
    u64* mw = s_w + img_l * W_U64_PER_IMG;
    const float* gx = x + (size_t)img * (HW * HW);

    // Stage merged weight pairs: 208 u64 = 104 ulonglong2 per image (guarded).
    {
        const ulonglong2* src =
            reinterpret_cast<const ulonglong2*>(g_Wd + (size_t)c * W_U64_PER_IMG);
        ulonglong2* dst = reinterpret_cast<ulonglong2*>(mw);
        for (int k = s; k < W_U64_PER_IMG / 2; k += 56)
            dst[k] = __ldg(src + k);
    }

    // Stage input: vector zero-fill padded tile, then coalesced float2
    // interior copy (constant-divisor indexing, no runtime div).
    {
        float4* z = reinterpret_cast<float4*>(my);
        for (int k = s; k < (PH * PH) / 4; k += 56)        // 1156 float4
            z[k] = make_float4(0.f, 0.f, 0.f, 0.f);
    }
    __syncthreads();
    {
        int col2 = s % 28;          // column pair 0..27
        int r0 = s / 28;            // 0 or 1
        const float2* g2 = reinterpret_cast<const float2*>(gx);
#pragma unroll
        for (int k = 0; k < 28; k++) {
            int r = r0 + 2 * k;
            float2 v = __ldg(g2 + r * 28 + col2);
            *reinterpret_cast<float2*>(my + (r + PAD) * PH + PAD + 2 * col2) = v;
        }
    }
    __syncthreads();

    float bb = __ldg(&g_bias[c]);
    u64 biasE = pack2(bb, 0.f);     // bias in even lane; lo+hi adds it once

    const float* rbase = my + y0 * PH + x0;   // padded coords, 16B aligned
    float* obase = out + (size_t)img * (HW * HW) + x0;

    // ============ Passes 1 & 2: ND=3, dfirst = 0 then 3 ====================
#pragma unroll 1
    for (int dfirst = 0; dfirst < 6; dfirst += 3) {
        u64 acc0[8], acc1[8], acc2[8];
#pragma unroll
        for (int q = 0; q < 8; q++) {
            acc0[q] = biasE; acc1[q] = biasE; acc2[q] = biasE;
        }

        const float* rb = rbase + dfirst * PH;
        float4 A[5], B[5], C[5];
        load5(A, rb + 0 * PH);
        load5(B, rb + 1 * PH);
        load5(C, rb + 2 * PH);

        u64 wE[7];
        loadW7(wE, mw + 0 * WSTRIDE);     // prologue: E(0)

#pragma unroll 1
        for (int w = 0; w < 12; w += 3) {
            u64 wO[7], wX[7];
            // step w: rows w..w+2 = A,B,C; E half in wE
            loadW7(wO, mw + w * WSTRIDE + 8);
            phase3<0>(acc0, acc1, acc2, A, B, C, wE);
            loadW7(wX, mw + (w + 1) * WSTRIDE);           // E(w+1)
            phase3<1>(acc0, acc1, acc2, A, B, C, wO);
            load5(A, rb + (w + 3) * PH);

            // step w+1: rows w+1..w+3 = B,C,A; E half in wX
            loadW7(wO, mw + (w + 1) * WSTRIDE + 8);
            phase3<0>(acc0, acc1, acc2, B, C, A, wX);
            loadW7(wX, mw + (w + 2) * WSTRIDE);           // E(w+2)
            phase3<1>(acc0, acc1, acc2, B, C, A, wO);
            load5(B, rb + (w + 4) * PH);

            // step w+2: rows w+2..w+4 = C,A,B; E half in wX
            loadW7(wO, mw + (w + 2) * WSTRIDE + 8);
            phase3<0>(acc0, acc1, acc2, C, A, B, wX);
            loadW7(wE, mw + (w + 3) * WSTRIDE);           // E(w+3) carry
            phase3<1>(acc0, acc1, acc2, C, A, B, wO);
            load5(C, rb + (w + 5) * PH);
        }
        {   // tail step 12: rows 12,13,14 = A,B,C; E half in wE
            u64 wO[7];
            loadW7(wO, mw + 12 * WSTRIDE + 8);
            phase3<0>(acc0, acc1, acc2, A, B, C, wE);
            phase3<1>(acc0, acc1, acc2, A, B, C, wO);
        }

        store_row(obase, y0 + dfirst + 0, acc0);
        store_row(obase, y0 + dfirst + 1, acc1);
        store_row(obase, y0 + dfirst + 2, acc2);
    }

    // ============ Pass 3: ND=1, d = 6 (rows 6..18) =========================
    {
        u64 acc[8];
#pragma unroll
        for (int q = 0; q < 8; q++) acc[q] = biasE;

        const float* rb = rbase + 6 * PH;
        float4 A[5], B[5];
        load5(A, rb + 0 * PH);

        u64 wE[7];
        loadW7(wE, mw + 0 * WSTRIDE);

#pragma unroll 1
        for (int w = 0; w < 12; w += 2) {
            u64 wO[7], wX[7];
            // step w: input A; E in wE
            loadW7(wO, mw + w * WSTRIDE + 8);
            load5(B, rb + (w + 1) * PH);
            phase1<0>(acc, A, wE);
            loadW7(wX, mw + (w + 1) * WSTRIDE);           // E(w+1)
            phase1<1>(acc, A, wO);
            // step w+1: input B; E in wX
            loadW7(wO, mw + (w + 1) * WSTRIDE + 8);
            load5(A, rb + (w + 2) * PH);
            phase1<0>(acc, B, wX);
            loadW7(wE, mw + (w + 2) * WSTRIDE);           // E(w+2) carry
            phase1<1>(acc, B, wO);
        }
        {   // tail step 12: input A; E in wE
            u64 wO[7];
            loadW7(wO, mw + 12 * WSTRIDE + 8);
            phase1<0>(acc, A, wE);
            phase1<1>(acc, A, wO);
        }

        store_row(obase, y0 + 6, acc);
    }
}

// ---------------------------------------------------------------------------
extern "C" void kernel_launch(void* const* d_in, const int* in_sizes, int n_in,
                              void* d_out, int out_size) {
    const float* x    = (const float*)d_in[0];
    const float* w_lk = (const float*)d_in[1];
    const float* w_b0 = (const float*)d_in[2];
    const float* w_b1 = (const float*)d_in[3];
    const float* w_b2 = (const float*)d_in[4];
    const float* w_b3 = (const float*)d_in[5];
    const float* w_b4 = (const float*)d_in[6];
    const float* w_b5 = (const float*)d_in[7];
    const float* gam  = (const float*)d_in[8];
    const float* bet  = (const float*)d_in[9];
    const float* mea  = (const float*)d_in[10];
    const float* var  = (const float*)d_in[11];
    float* out = (float*)d_out;

    merge_kernel<<<C_CH, 224>>>(w_lk, w_b0, w_b1, w_b2, w_b3, w_b4, w_b5,
                                gam, bet, mea, var);

    cudaFuncSetAttribute(conv13_kernel,
                         cudaFuncAttributeMaxDynamicSharedMemorySize,
                         SMEM_BYTES);
    int grid = (NB * C_CH) / IMG_PER_BLK;  // 3072
    conv13_kernel<<<grid, THREADS, SMEM_BYTES>>>(x, out);
}